// round 2
// baseline (speedup 1.0000x reference)
#include <cuda_runtime.h>
#include <cstdint>

#define MAXN 100000
#define MAXE 1600000

// ---------------- device scratch (no allocs allowed) ----------------
__device__ __align__(16) float g_xl[(size_t)MAXN * 128];   // x@Wl_g + bl_g
__device__ __align__(16) float g_xr[(size_t)MAXN * 128];   // x@Wr_g + br_g
__device__ float g_xld[MAXN * 2];
__device__ float g_xrd[MAXN * 2];
__device__ float g_sdec[MAXN];
__device__ float g_accdec[MAXN * 2];
__device__ int   g_cnt0[MAXN], g_cnt1[MAXN];
__device__ int   g_off0[MAXN + 1], g_off1[MAXN + 1];
__device__ int   g_cur0[MAXN], g_cur1[MAXN];
__device__ int   g_csr0[MAXE], g_csr1[MAXE];
__device__ int   g_dec[MAXN];
__device__ float g_gate[MAXN];
__device__ int   g_part[512];
__device__ int   g_is64;

// ---------------- helpers ----------------
__device__ __forceinline__ float lrelu(float v) { return v > 0.f ? v : 0.2f * v; }

__device__ __forceinline__ float warp_sum(float v) {
#pragma unroll
    for (int o = 16; o; o >>= 1) v += __shfl_xor_sync(0xffffffffu, v, o);
    return v;
}

__device__ __forceinline__ unsigned long long pk2(float a, float b) {
    unsigned long long r;
    asm("mov.b64 %0, {%1, %2};" : "=l"(r) : "f"(a), "f"(b));
    return r;
}
__device__ __forceinline__ void upk2(unsigned long long v, float& a, float& b) {
    asm("mov.b64 {%0, %1}, %2;" : "=f"(a), "=f"(b) : "l"(v));
}
__device__ __forceinline__ unsigned long long ffma2(unsigned long long a,
                                                    unsigned long long b,
                                                    unsigned long long c) {
    unsigned long long d;
    asm("fma.rn.f32x2 %0, %1, %2, %3;" : "=l"(d) : "l"(a), "l"(b), "l"(c));
    return d;
}

// ---------------- dtype detection ----------------
// If edges are int64, every odd int32 word (high word of a value < 2^31) is 0.
__global__ void k_detect(const int* __restrict__ e) {
    int t = threadIdx.x;  // 32 threads
    int nz = e[2 * t + 1] | e[2 * (t + 32) + 1] | e[2 * (t + 64) + 1] | e[2 * (t + 96) + 1];
    unsigned m = __ballot_sync(0xffffffffu, nz != 0);
    if (t == 0) g_is64 = (m == 0) ? 1 : 0;
}

// ---------------- zero scratch (must run every replay) ----------------
__global__ void k_zero(int n) {
    int i = blockIdx.x * blockDim.x + threadIdx.x;
    if (i < 2 * n) {
        g_accdec[i] = 0.f;
        if (i < n) { g_sdec[i] = 0.f; g_cnt0[i] = 0; g_cnt1[i] = 0; }
    }
}

// ---------------- big SGEMM: Y[n,128] = X[n,128] @ W[128,128] + bias ----------------
// which==0 -> write g_xl, which==1 -> write g_xr  (globals accessed from DEVICE
// code only; passing __device__ arrays as host-side kernel args is invalid).
__global__ __launch_bounds__(256, 2) void k_sgemm128(const float* __restrict__ X,
                                                     const float* __restrict__ W,
                                                     const float* __restrict__ bias,
                                                     int which, int n) {
    float* __restrict__ Y = which ? g_xr : g_xl;
    __shared__ __align__(16) float As[16][136];  // [k][m], padded
    __shared__ __align__(16) float Bs[16][128];  // [k][ncol]
    const int tid = threadIdx.x;
    const int mBase = blockIdx.x * 128;
    const int r0 = (tid >> 4) * 4;
    const int c0 = (tid & 15) * 4;

    unsigned long long acc[8][4];
#pragma unroll
    for (int i = 0; i < 8; i++)
#pragma unroll
        for (int j = 0; j < 4; j++) acc[i][j] = 0ull;

#pragma unroll 1
    for (int kb = 0; kb < 8; kb++) {
        const int k0 = kb * 16;
        // load A tile (128 rows x 16 k) transposed
#pragma unroll
        for (int rep = 0; rep < 2; rep++) {
            int f = tid + rep * 256;        // 0..511
            int row = f >> 2;               // 0..127
            int cq = f & 3;                 // float4 within row
            float4 v = make_float4(0.f, 0.f, 0.f, 0.f);
            int gr = mBase + row;
            if (gr < n) v = *(const float4*)(X + (size_t)gr * 128 + k0 + cq * 4);
            As[cq * 4 + 0][row] = v.x;
            As[cq * 4 + 1][row] = v.y;
            As[cq * 4 + 2][row] = v.z;
            As[cq * 4 + 3][row] = v.w;
        }
        // load B tile (16 k x 128 cols)
#pragma unroll
        for (int rep = 0; rep < 2; rep++) {
            int f = tid + rep * 256;
            int krow = f >> 5;              // 0..15
            int cc = (f & 31) * 4;          // 0..124
            *(float4*)&Bs[krow][cc] = *(const float4*)(W + (size_t)(k0 + krow) * 128 + cc);
        }
        __syncthreads();
#pragma unroll
        for (int kk = 0; kk < 16; kk++) {
            float4 aLo = *(const float4*)&As[kk][r0];
            float4 aHi = *(const float4*)&As[kk][64 + r0];
            float4 bLo = *(const float4*)&Bs[kk][c0];
            float4 bHi = *(const float4*)&Bs[kk][64 + c0];
            unsigned long long bp0 = pk2(bLo.x, bLo.y);
            unsigned long long bp1 = pk2(bLo.z, bLo.w);
            unsigned long long bp2 = pk2(bHi.x, bHi.y);
            unsigned long long bp3 = pk2(bHi.z, bHi.w);
            float ar[8] = {aLo.x, aLo.y, aLo.z, aLo.w, aHi.x, aHi.y, aHi.z, aHi.w};
#pragma unroll
            for (int i = 0; i < 8; i++) {
                unsigned long long ap = pk2(ar[i], ar[i]);
                acc[i][0] = ffma2(ap, bp0, acc[i][0]);
                acc[i][1] = ffma2(ap, bp1, acc[i][1]);
                acc[i][2] = ffma2(ap, bp2, acc[i][2]);
                acc[i][3] = ffma2(ap, bp3, acc[i][3]);
            }
        }
        __syncthreads();
    }

    float4 bLo = *(const float4*)(bias + c0);
    float4 bHi = *(const float4*)(bias + 64 + c0);
#pragma unroll
    for (int i = 0; i < 8; i++) {
        int row = mBase + ((i < 4) ? (r0 + i) : (64 + r0 + (i - 4)));
        if (row < n) {
            float y0, y1, y2, y3;
            upk2(acc[i][0], y0, y1);
            upk2(acc[i][1], y2, y3);
            *(float4*)(Y + (size_t)row * 128 + c0) =
                make_float4(y0 + bLo.x, y1 + bLo.y, y2 + bLo.z, y3 + bLo.w);
            upk2(acc[i][2], y0, y1);
            upk2(acc[i][3], y2, y3);
            *(float4*)(Y + (size_t)row * 128 + 64 + c0) =
                make_float4(y0 + bHi.x, y1 + bHi.y, y2 + bHi.z, y3 + bHi.w);
        }
    }
}

// ---------------- decision projections: xl_d/xr_d = x@W_d + b_d (warp/node) ----------------
__global__ void k_gemmd(const float* __restrict__ x,
                        const float* __restrict__ wl, const float* __restrict__ wr,
                        const float* __restrict__ bl, const float* __restrict__ br, int n) {
    int w = (blockIdx.x * blockDim.x + threadIdx.x) >> 5;
    if (w >= n) return;
    int lane = threadIdx.x & 31;
    float4 xv = __ldg((const float4*)(x + (size_t)w * 128) + lane);
    float xs[4] = {xv.x, xv.y, xv.z, xv.w};
    const float2* WL = (const float2*)wl;
    const float2* WR = (const float2*)wr;
    float pl0 = 0.f, pl1 = 0.f, pr0 = 0.f, pr1 = 0.f;
#pragma unroll
    for (int j = 0; j < 4; j++) {
        float2 a = __ldg(&WL[lane * 4 + j]);
        float2 b = __ldg(&WR[lane * 4 + j]);
        pl0 += xs[j] * a.x; pl1 += xs[j] * a.y;
        pr0 += xs[j] * b.x; pr1 += xs[j] * b.y;
    }
    pl0 = warp_sum(pl0); pl1 = warp_sum(pl1);
    pr0 = warp_sum(pr0); pr1 = warp_sum(pr1);
    if (lane == 0) {
        g_xld[2 * w]     = pl0 + __ldg(&bl[0]);
        g_xld[2 * w + 1] = pl1 + __ldg(&bl[1]);
        g_xrd[2 * w]     = pr0 + __ldg(&br[0]);
        g_xrd[2 * w + 1] = pr1 + __ldg(&br[1]);
    }
}

// ---------------- decision edge pass (no-max softmax, atomics) ----------------
__global__ void k_dec_edges(const int* __restrict__ e, const float* __restrict__ attd, int E) {
    int i = blockIdx.x * blockDim.x + threadIdx.x;
    if (i >= E) return;
    int is64 = g_is64;
    int s = is64 ? e[2 * i] : e[i];
    int d = is64 ? e[2 * (E + i)] : e[E + i];
    float xl0 = g_xld[2 * s], xl1 = g_xld[2 * s + 1];
    float xr0 = g_xrd[2 * d], xr1 = g_xrd[2 * d + 1];
    float a0 = __ldg(&attd[0]), a1 = __ldg(&attd[1]);
    float ee = a0 * lrelu(xl0 + xr0) + a1 * lrelu(xl1 + xr1);
    float w = expf(fminf(ee, 75.f));
    atomicAdd(&g_sdec[d], w);
    atomicAdd(&g_accdec[2 * d], w * xl0);
    atomicAdd(&g_accdec[2 * d + 1], w * xl1);
}

// ---------------- decision finalize: self loop + logits + hard gumbel ----------------
__global__ void k_dec_final(const float* __restrict__ gum, const float* __restrict__ attd,
                            const float* __restrict__ biasd, int n) {
    int i = blockIdx.x * blockDim.x + threadIdx.x;
    if (i >= n) return;
    float xl0 = g_xld[2 * i], xl1 = g_xld[2 * i + 1];
    float xr0 = g_xrd[2 * i], xr1 = g_xrd[2 * i + 1];
    float a0 = __ldg(&attd[0]), a1 = __ldg(&attd[1]);
    float ee = a0 * lrelu(xl0 + xr0) + a1 * lrelu(xl1 + xr1);
    float w = expf(fminf(ee, 75.f));
    float s = g_sdec[i] + w;
    float A0 = g_accdec[2 * i] + w * xl0;
    float A1 = g_accdec[2 * i + 1] + w * xl1;
    float inv = 1.f / (s + 1e-16f);
    float l0 = A0 * inv + __ldg(&biasd[0]);
    float l1 = A1 * inv + __ldg(&biasd[1]);
    float z0 = (l0 + gum[2 * i]) * 2.0f;       // /tau, tau=0.5
    float z1 = (l1 + gum[2 * i + 1]) * 2.0f;
    int c = (z0 >= z1) ? 0 : 1;                // argmax, first-wins tie
    float du = (c == 0) ? (z1 - z0) : (z0 - z1);  // <= 0
    float p = 1.f / (1.f + expf(du));          // softmax prob of chosen class
    volatile float t = 1.0f + p;               // keep (1+p)-p unfolded
    g_dec[i] = c;
    g_gate[i] = t - p;
}

// ---------------- CSR build ----------------
__global__ void k_hist(const int* __restrict__ e, int set, int E) {
    int i = blockIdx.x * blockDim.x + threadIdx.x;
    if (i >= E) return;
    int d = g_is64 ? e[2 * (E + i)] : e[E + i];
    atomicAdd(set ? &g_cnt1[d] : &g_cnt0[d], 1);
}

__global__ void k_scan1(int n, int nb) {  // grid 2*nb, 512 thr
    int set = (blockIdx.x >= nb) ? 1 : 0;
    int b = blockIdx.x - set * nb;
    int i = b * 512 + threadIdx.x;
    const int* cnt = set ? g_cnt1 : g_cnt0;
    __shared__ int sm[512];
    sm[threadIdx.x] = (i < n) ? cnt[i] : 0;
    __syncthreads();
    for (int o = 256; o; o >>= 1) {
        if (threadIdx.x < o) sm[threadIdx.x] += sm[threadIdx.x + o];
        __syncthreads();
    }
    if (threadIdx.x == 0) g_part[set * 256 + b] = sm[0];
}

__global__ void k_scan2(int n, int nb) {  // 1 block, 256 thr
    __shared__ int sm[256];
    int t = threadIdx.x;
    for (int set = 0; set < 2; set++) {
        int v = (t < nb) ? g_part[set * 256 + t] : 0;
        sm[t] = v;
        __syncthreads();
        for (int o = 1; o < 256; o <<= 1) {
            int x = (t >= o) ? sm[t - o] : 0;
            __syncthreads();
            sm[t] += x;
            __syncthreads();
        }
        int incl = sm[t];
        if (t < nb) g_part[set * 256 + t] = incl - v;
        if (t == nb - 1) { if (set) g_off1[n] = incl; else g_off0[n] = incl; }
        __syncthreads();
    }
}

__global__ void k_scan3(int n, int nb) {  // grid 2*nb, 512 thr
    int set = (blockIdx.x >= nb) ? 1 : 0;
    int b = blockIdx.x - set * nb;
    int i = b * 512 + threadIdx.x;
    const int* cnt = set ? g_cnt1 : g_cnt0;
    __shared__ int sm[512];
    int t = threadIdx.x;
    int v = (i < n) ? cnt[i] : 0;
    sm[t] = v;
    __syncthreads();
    for (int o = 1; o < 512; o <<= 1) {
        int x = (t >= o) ? sm[t - o] : 0;
        __syncthreads();
        sm[t] += x;
        __syncthreads();
    }
    int excl = sm[t] - v;
    if (i < n) {
        int off = g_part[set * 256 + b] + excl;
        if (set) { g_off1[i] = off; g_cur1[i] = off; }
        else     { g_off0[i] = off; g_cur0[i] = off; }
    }
}

__global__ void k_scatter(const int* __restrict__ e, int set, int E) {
    int i = blockIdx.x * blockDim.x + threadIdx.x;
    if (i >= E) return;
    int is64 = g_is64;
    int s = is64 ? e[2 * i] : e[i];
    int d = is64 ? e[2 * (E + i)] : e[E + i];
    int p = atomicAdd(set ? &g_cur1[d] : &g_cur0[d], 1);
    if (p >= 0 && p < MAXE) { if (set) g_csr1[p] = s; else g_csr0[p] = s; }
}

// ---------------- gated aggregation: warp per node, single-sweep softmax ----------------
__global__ __launch_bounds__(256) void k_agg(const float* __restrict__ att,
                                             const float* __restrict__ bias,
                                             float* __restrict__ out, int n) {
    int w = (blockIdx.x * blockDim.x + threadIdx.x) >> 5;
    if (w >= n) return;
    int lane = threadIdx.x & 31;
    int k = g_dec[w];
    const int* csr = k ? g_csr1 : g_csr0;
    const int* off = k ? g_off1 : g_off0;
    int beg = off[w], end = off[w + 1];

    float4 a4 = *(const float4*)(att + lane * 4);
    const float4* xlp = (const float4*)g_xl;
    float4 r4 = *((const float4*)(g_xr) + (size_t)w * 32 + lane);

    // self loop
    float4 v = xlp[(size_t)w * 32 + lane];
    float p = a4.x * lrelu(v.x + r4.x) + a4.y * lrelu(v.y + r4.y) +
              a4.z * lrelu(v.z + r4.z) + a4.w * lrelu(v.w + r4.w);
    float e = warp_sum(p);
    float wt = __expf(fminf(e, 75.f));
    float s = wt;
    float4 acc = make_float4(wt * v.x, wt * v.y, wt * v.z, wt * v.w);

#pragma unroll 2
    for (int j = beg; j < end; j++) {
        int src = __ldg(&csr[j]);
        float4 u = xlp[(size_t)src * 32 + lane];
        float q = a4.x * lrelu(u.x + r4.x) + a4.y * lrelu(u.y + r4.y) +
                  a4.z * lrelu(u.z + r4.z) + a4.w * lrelu(u.w + r4.w);
        float e2 = warp_sum(q);
        float w2 = __expf(fminf(e2, 75.f));
        s += w2;
        acc.x += w2 * u.x; acc.y += w2 * u.y; acc.z += w2 * u.z; acc.w += w2 * u.w;
    }

    float g = g_gate[w];
    float inv = g / (s + 1e-16f);
    float4 b4 = *(const float4*)(bias + lane * 4);
    float4 o4 = make_float4(acc.x * inv + b4.x * g, acc.y * inv + b4.y * g,
                            acc.z * inv + b4.z * g, acc.w * inv + b4.w * g);
    *((float4*)out + (size_t)w * 32 + lane) = o4;
}

// ---------------- launcher ----------------
extern "C" void kernel_launch(void* const* d_in, const int* in_sizes, int n_in,
                              void* d_out, int out_size) {
    const float* x      = (const float*)d_in[0];
    const int*   e_dec  = (const int*)d_in[1];
    const int*   e0     = (const int*)d_in[2];
    const int*   e1     = (const int*)d_in[3];
    const float* gum    = (const float*)d_in[4];
    const float* Wl_g   = (const float*)d_in[5];
    const float* Wr_g   = (const float*)d_in[6];
    const float* bl_g   = (const float*)d_in[7];
    const float* br_g   = (const float*)d_in[8];
    const float* att_g  = (const float*)d_in[9];
    const float* bias_g = (const float*)d_in[10];
    const float* Wl_d   = (const float*)d_in[11];
    const float* Wr_d   = (const float*)d_in[12];
    const float* bl_d   = (const float*)d_in[13];
    const float* br_d   = (const float*)d_in[14];
    const float* att_d  = (const float*)d_in[15];
    const float* bias_d = (const float*)d_in[16];
    float* out = (float*)d_out;

    const int n = in_sizes[0] / 128;
    const int E = in_sizes[1] / 2;
    const int nb = (n + 511) / 512;

    k_detect<<<1, 32>>>(e_dec);
    k_zero<<<(2 * n + 255) / 256, 256>>>(n);

    const int gBlocks = (n + 127) / 128;
    k_sgemm128<<<gBlocks, 256>>>(x, Wl_g, bl_g, 0, n);
    k_sgemm128<<<gBlocks, 256>>>(x, Wr_g, br_g, 1, n);
    k_gemmd<<<(n + 7) / 8, 256>>>(x, Wl_d, Wr_d, bl_d, br_d, n);

    const int eBlocks = (E + 255) / 256;
    k_hist<<<eBlocks, 256>>>(e0, 0, E);
    k_hist<<<eBlocks, 256>>>(e1, 1, E);
    k_dec_edges<<<eBlocks, 256>>>(e_dec, att_d, E);

    k_scan1<<<2 * nb, 512>>>(n, nb);
    k_scan2<<<1, 256>>>(n, nb);
    k_scan3<<<2 * nb, 512>>>(n, nb);

    k_scatter<<<eBlocks, 256>>>(e0, 0, E);
    k_scatter<<<eBlocks, 256>>>(e1, 1, E);

    k_dec_final<<<(n + 255) / 256, 256>>>(gum, att_d, bias_d, n);

    k_agg<<<(n + 7) / 8, 256>>>(att_g, bias_g, out, n);
}

// round 4
// speedup vs baseline: 1.1385x; 1.1385x over previous
#include <cuda_runtime.h>
#include <cuda_bf16.h>
#include <cstdint>

#define MAXN 100000
#define MAXE 1600000

// ---------------- device scratch ----------------
__device__ __align__(16) float g_xl[(size_t)MAXN * 128];
__device__ __align__(16) float g_xr[(size_t)MAXN * 128];
__device__ float g_xld[MAXN * 2];
__device__ float g_xrd[MAXN * 2];
__device__ float g_sdec[MAXN];
__device__ float g_accdec[MAXN * 2];
__device__ int   g_cnt0[MAXN], g_cnt1[MAXN];
__device__ int   g_off0[MAXN + 1], g_off1[MAXN + 1];
__device__ int   g_cur0[MAXN], g_cur1[MAXN];
__device__ int   g_csr0[MAXE], g_csr1[MAXE];
__device__ int   g_part[512];
__device__ int   g_is64;
// W^T bf16 hi/lo, layout [n][k] (k contiguous): [Wl_hi, Wl_lo, Wr_hi, Wr_lo]
__device__ __align__(16) __nv_bfloat16 g_wtb[4][16384];

// ---------------- helpers ----------------
__device__ __forceinline__ float lrelu(float v) { return v > 0.f ? v : 0.2f * v; }

__device__ __forceinline__ float warp_sum(float v) {
#pragma unroll
    for (int o = 16; o; o >>= 1) v += __shfl_xor_sync(0xffffffffu, v, o);
    return v;
}

__device__ __forceinline__ uint32_t smem_u32(const void* p) {
    uint32_t a;
    asm("{ .reg .u64 t; cvta.to.shared.u64 t, %1; cvt.u32.u64 %0, t; }" : "=r"(a) : "l"(p));
    return a;
}

__device__ __forceinline__ void ldsm_x4(uint32_t* r, uint32_t addr) {
    asm volatile("ldmatrix.sync.aligned.m8n8.x4.shared.b16 {%0,%1,%2,%3}, [%4];"
                 : "=r"(r[0]), "=r"(r[1]), "=r"(r[2]), "=r"(r[3]) : "r"(addr));
}
__device__ __forceinline__ void ldsm_x2(uint32_t* r, uint32_t addr) {
    asm volatile("ldmatrix.sync.aligned.m8n8.x2.shared.b16 {%0,%1}, [%2];"
                 : "=r"(r[0]), "=r"(r[1]) : "r"(addr));
}
__device__ __forceinline__ void mma16816(float* d, const uint32_t* a, const uint32_t* b) {
    asm volatile(
        "mma.sync.aligned.m16n8k16.row.col.f32.bf16.bf16.f32 "
        "{%0,%1,%2,%3}, {%4,%5,%6,%7}, {%8,%9}, {%0,%1,%2,%3};"
        : "+f"(d[0]), "+f"(d[1]), "+f"(d[2]), "+f"(d[3])
        : "r"(a[0]), "r"(a[1]), "r"(a[2]), "r"(a[3]), "r"(b[0]), "r"(b[1]));
}

// ---------------- dtype detection ----------------
__global__ void k_detect(const int* __restrict__ e) {
    int t = threadIdx.x;
    int nz = e[2 * t + 1] | e[2 * (t + 32) + 1] | e[2 * (t + 64) + 1] | e[2 * (t + 96) + 1];
    unsigned m = __ballot_sync(0xffffffffu, nz != 0);
    if (t == 0) g_is64 = (m == 0) ? 1 : 0;
}

// ---------------- zero scratch ----------------
__global__ void k_zero(int n) {
    int i = blockIdx.x * blockDim.x + threadIdx.x;
    if (i < 2 * n) {
        g_accdec[i] = 0.f;
        if (i < n) { g_sdec[i] = 0.f; g_cnt0[i] = 0; g_cnt1[i] = 0; }
    }
}

// ---------------- W^T bf16 hi/lo prep: g_wtb[.][n*128+k] ----------------
__global__ void k_prepW(const float* __restrict__ wl, const float* __restrict__ wr) {
    int i = blockIdx.x * blockDim.x + threadIdx.x;  // 0..32767
    if (i >= 32768) return;
    int m = i >> 14;
    int rem = i & 16383;
    int k = rem >> 7, nn = rem & 127;   // coalesced read over nn
    float w = (m ? wr : wl)[k * 128 + nn];
    __nv_bfloat16 hi = __float2bfloat16(w);
    __nv_bfloat16 lo = __float2bfloat16(w - __bfloat162float(hi));
    g_wtb[2 * m + 0][nn * 128 + k] = hi;
    g_wtb[2 * m + 1][nn * 128 + k] = lo;
}

// ---------------- bf16 split-K mma.sync GEMM: Y[n,128] = X @ W + bias ----------------
// 3-term: Ah*Bh + Ah*Bl + Al*Bh.  smem slabs of K=64, padded rows of 72 bf16.
#define SLAB_ROW 72                      // bf16 per smem row (64 + 8 pad)
#define SM_A_HI 0
#define SM_A_LO 18432
#define SM_B_HI 36864
#define SM_B_LO 55296
#define SM_GEMM_TOTAL 73728

__global__ __launch_bounds__(256, 2) void k_mma(const float* __restrict__ X,
                                                const float* __restrict__ bias,
                                                int which, int n) {
    extern __shared__ __align__(16) unsigned char sm[];
    __nv_bfloat16* Ah = (__nv_bfloat16*)(sm + SM_A_HI);
    __nv_bfloat16* Al = (__nv_bfloat16*)(sm + SM_A_LO);
    __nv_bfloat16* Bh = (__nv_bfloat16*)(sm + SM_B_HI);
    __nv_bfloat16* Bl = (__nv_bfloat16*)(sm + SM_B_LO);

    const int tid = threadIdx.x;
    const int w = tid >> 5;
    const int lane = tid & 31;
    const int wm = w & 3;     // m quarter (32 rows)
    const int wn = w >> 1 & 2;// not used; compute below properly
    const int wcol = (w >> 2) * 64;  // n half (64 cols)
    const int mBase = blockIdx.x * 128;

    float acc[2][8][4];
#pragma unroll
    for (int a = 0; a < 2; a++)
#pragma unroll
        for (int b = 0; b < 8; b++)
#pragma unroll
            for (int c = 0; c < 4; c++) acc[a][b][c] = 0.f;

    const __nv_bfloat16* WH = g_wtb[2 * which];
    const __nv_bfloat16* WL = g_wtb[2 * which + 1];

#pragma unroll
    for (int slab = 0; slab < 2; slab++) {
        const int k0 = slab * 64;
        // ---- A slab: convert 128 rows x 64 k of X into bf16 hi/lo ----
#pragma unroll
        for (int it = 0; it < 8; it++) {
            int idx = tid + it * 256;     // 0..2047 = 128 rows x 16 float4
            int row = idx >> 4;
            int q = idx & 15;
            float4 v = make_float4(0.f, 0.f, 0.f, 0.f);
            int gr = mBase + row;
            if (gr < n) v = __ldg((const float4*)(X + (size_t)gr * 128 + k0) + q);
            __nv_bfloat162 h01 = __floats2bfloat162_rn(v.x, v.y);
            __nv_bfloat162 h23 = __floats2bfloat162_rn(v.z, v.w);
            float2 f01 = __bfloat1622float2(h01);
            float2 f23 = __bfloat1622float2(h23);
            __nv_bfloat162 l01 = __floats2bfloat162_rn(v.x - f01.x, v.y - f01.y);
            __nv_bfloat162 l23 = __floats2bfloat162_rn(v.z - f23.x, v.w - f23.y);
            uint2 hw, lw;
            hw.x = *(uint32_t*)&h01; hw.y = *(uint32_t*)&h23;
            lw.x = *(uint32_t*)&l01; lw.y = *(uint32_t*)&l23;
            *(uint2*)&Ah[row * SLAB_ROW + q * 4] = hw;
            *(uint2*)&Al[row * SLAB_ROW + q * 4] = lw;
        }
        // ---- B slab: linear copy from pre-transposed g_wtb ----
#pragma unroll
        for (int it = 0; it < 8; it++) {
            int idx = tid + it * 256;     // 0..2047: ver(2) x 128 rows x 8 float4
            int ver = idx >> 10;
            int r = (idx >> 3) & 127;
            int j = idx & 7;
            const float4* src = (const float4*)((ver ? WL : WH) + r * 128 + k0);
            float4 val = __ldg(src + j);
            __nv_bfloat16* dst = (ver ? Bl : Bh) + r * SLAB_ROW + j * 8;
            *(float4*)dst = val;
        }
        __syncthreads();

        // ---- compute: 4 k16 blocks ----
#pragma unroll
        for (int kb = 0; kb < 4; kb++) {
            uint32_t afh[2][4], afl[2][4];
#pragma unroll
            for (int mb = 0; mb < 2; mb++) {
                int row = wm * 32 + mb * 16 + (lane & 7) + ((lane & 8) ? 8 : 0);
                int colb = kb * 32 + ((lane & 16) ? 16 : 0);
                ldsm_x4(afh[mb], smem_u32(&Ah[row * SLAB_ROW]) + colb);
                ldsm_x4(afl[mb], smem_u32(&Al[row * SLAB_ROW]) + colb);
            }
#pragma unroll
            for (int nb = 0; nb < 8; nb++) {
                int nrow = wcol + nb * 8 + (lane & 7);
                int colb = kb * 32 + ((lane & 8) ? 16 : 0);
                uint32_t bh[2], bl[2];
                ldsm_x2(bh, smem_u32(&Bh[nrow * SLAB_ROW]) + colb);
                ldsm_x2(bl, smem_u32(&Bl[nrow * SLAB_ROW]) + colb);
#pragma unroll
                for (int mb = 0; mb < 2; mb++) {
                    mma16816(acc[mb][nb], afh[mb], bh);
                    mma16816(acc[mb][nb], afh[mb], bl);
                    mma16816(acc[mb][nb], afl[mb], bh);
                }
            }
        }
        __syncthreads();
    }

    // ---- epilogue ----
    float* dst = which ? g_xr : g_xl;
    int g = lane >> 2, tg = lane & 3;
#pragma unroll
    for (int mb = 0; mb < 2; mb++) {
#pragma unroll
        for (int nb = 0; nb < 8; nb++) {
            int col = wcol + nb * 8 + 2 * tg;
            float2 bv = __ldg((const float2*)(bias + col));
            int row0 = mBase + wm * 32 + mb * 16 + g;
            if (row0 < n) {
                float2 o = make_float2(acc[mb][nb][0] + bv.x, acc[mb][nb][1] + bv.y);
                *(float2*)(dst + (size_t)row0 * 128 + col) = o;
            }
            int row1 = row0 + 8;
            if (row1 < n) {
                float2 o = make_float2(acc[mb][nb][2] + bv.x, acc[mb][nb][3] + bv.y);
                *(float2*)(dst + (size_t)row1 * 128 + col) = o;
            }
        }
    }
}

// ---------------- decision projections (exact fp32) ----------------
__global__ void k_gemmd(const float* __restrict__ x,
                        const float* __restrict__ wl, const float* __restrict__ wr,
                        const float* __restrict__ bl, const float* __restrict__ br, int n) {
    int w = (blockIdx.x * blockDim.x + threadIdx.x) >> 5;
    if (w >= n) return;
    int lane = threadIdx.x & 31;
    float4 xv = __ldg((const float4*)(x + (size_t)w * 128) + lane);
    float xs[4] = {xv.x, xv.y, xv.z, xv.w};
    const float2* WL = (const float2*)wl;
    const float2* WR = (const float2*)wr;
    float pl0 = 0.f, pl1 = 0.f, pr0 = 0.f, pr1 = 0.f;
#pragma unroll
    for (int j = 0; j < 4; j++) {
        float2 a = __ldg(&WL[lane * 4 + j]);
        float2 b = __ldg(&WR[lane * 4 + j]);
        pl0 += xs[j] * a.x; pl1 += xs[j] * a.y;
        pr0 += xs[j] * b.x; pr1 += xs[j] * b.y;
    }
    pl0 = warp_sum(pl0); pl1 = warp_sum(pl1);
    pr0 = warp_sum(pr0); pr1 = warp_sum(pr1);
    if (lane == 0) {
        g_xld[2 * w]     = pl0 + __ldg(&bl[0]);
        g_xld[2 * w + 1] = pl1 + __ldg(&bl[1]);
        g_xrd[2 * w]     = pr0 + __ldg(&br[0]);
        g_xrd[2 * w + 1] = pr1 + __ldg(&br[1]);
    }
}

// ---------------- fused edge pass: hist(e0) | hist(e1) | decision edges ----------------
__global__ void k_edges(const int* __restrict__ e0, const int* __restrict__ e1,
                        const int* __restrict__ ed, const float* __restrict__ attd,
                        int E, int eBlocks) {
    int role = blockIdx.x / eBlocks;
    int i = (blockIdx.x - role * eBlocks) * blockDim.x + threadIdx.x;
    if (i >= E) return;
    int is64 = g_is64;
    if (role == 0) {
        int d = is64 ? e0[2 * (E + i)] : e0[E + i];
        atomicAdd(&g_cnt0[d], 1);
    } else if (role == 1) {
        int d = is64 ? e1[2 * (E + i)] : e1[E + i];
        atomicAdd(&g_cnt1[d], 1);
    } else {
        int s = is64 ? ed[2 * i] : ed[i];
        int d = is64 ? ed[2 * (E + i)] : ed[E + i];
        float xl0 = g_xld[2 * s], xl1 = g_xld[2 * s + 1];
        float xr0 = g_xrd[2 * d], xr1 = g_xrd[2 * d + 1];
        float a0 = __ldg(&attd[0]), a1 = __ldg(&attd[1]);
        float ee = a0 * lrelu(xl0 + xr0) + a1 * lrelu(xl1 + xr1);
        float w = expf(fminf(ee, 75.f));
        atomicAdd(&g_sdec[d], w);
        atomicAdd(&g_accdec[2 * d], w * xl0);
        atomicAdd(&g_accdec[2 * d + 1], w * xl1);
    }
}

// ---------------- scans ----------------
__global__ void k_scan1(int n, int nb) {
    int set = (blockIdx.x >= nb) ? 1 : 0;
    int b = blockIdx.x - set * nb;
    int i = b * 512 + threadIdx.x;
    const int* cnt = set ? g_cnt1 : g_cnt0;
    __shared__ int smem[512];
    smem[threadIdx.x] = (i < n) ? cnt[i] : 0;
    __syncthreads();
    for (int o = 256; o; o >>= 1) {
        if (threadIdx.x < o) smem[threadIdx.x] += smem[threadIdx.x + o];
        __syncthreads();
    }
    if (threadIdx.x == 0) g_part[set * 256 + b] = smem[0];
}

__global__ void k_scan2(int n, int nb) {
    __shared__ int smem[256];
    int t = threadIdx.x;
    for (int set = 0; set < 2; set++) {
        int v = (t < nb) ? g_part[set * 256 + t] : 0;
        smem[t] = v;
        __syncthreads();
        for (int o = 1; o < 256; o <<= 1) {
            int x = (t >= o) ? smem[t - o] : 0;
            __syncthreads();
            smem[t] += x;
            __syncthreads();
        }
        int incl = smem[t];
        if (t < nb) g_part[set * 256 + t] = incl - v;
        if (t == nb - 1) { if (set) g_off1[n] = incl; else g_off0[n] = incl; }
        __syncthreads();
    }
}

__global__ void k_scan3(int n, int nb) {
    int set = (blockIdx.x >= nb) ? 1 : 0;
    int b = blockIdx.x - set * nb;
    int i = b * 512 + threadIdx.x;
    const int* cnt = set ? g_cnt1 : g_cnt0;
    __shared__ int smem[512];
    int t = threadIdx.x;
    int v = (i < n) ? cnt[i] : 0;
    smem[t] = v;
    __syncthreads();
    for (int o = 1; o < 512; o <<= 1) {
        int x = (t >= o) ? smem[t - o] : 0;
        __syncthreads();
        smem[t] += x;
        __syncthreads();
    }
    int excl = smem[t] - v;
    if (i < n) {
        int off = g_part[set * 256 + b] + excl;
        if (set) { g_off1[i] = off; g_cur1[i] = off; }
        else     { g_off0[i] = off; g_cur0[i] = off; }
    }
}

// ---------------- fused scatter ----------------
__global__ void k_scatter2(const int* __restrict__ e0, const int* __restrict__ e1,
                           int E, int eBlocks) {
    int set = (blockIdx.x >= eBlocks) ? 1 : 0;
    int i = (blockIdx.x - set * eBlocks) * blockDim.x + threadIdx.x;
    if (i >= E) return;
    int is64 = g_is64;
    const int* e = set ? e1 : e0;
    int s = is64 ? e[2 * i] : e[i];
    int d = is64 ? e[2 * (E + i)] : e[E + i];
    int p = atomicAdd(set ? &g_cur1[d] : &g_cur0[d], 1);
    if (p >= 0 && p < MAXE) { if (set) g_csr1[p] = s; else g_csr0[p] = s; }
}

// ---------------- gated aggregation (decision folded in) ----------------
__global__ __launch_bounds__(256) void k_agg(const float* __restrict__ att,
                                             const float* __restrict__ bias,
                                             const float* __restrict__ gum,
                                             const float* __restrict__ attd,
                                             const float* __restrict__ biasd,
                                             float* __restrict__ out, int n) {
    int w = (blockIdx.x * blockDim.x + threadIdx.x) >> 5;
    if (w >= n) return;
    int lane = threadIdx.x & 31;

    // --- decision (uniform scalar math, all lanes) ---
    int k;
    float g;
    {
        float xl0 = g_xld[2 * w], xl1 = g_xld[2 * w + 1];
        float xr0 = g_xrd[2 * w], xr1 = g_xrd[2 * w + 1];
        float a0 = __ldg(&attd[0]), a1 = __ldg(&attd[1]);
        float ee = a0 * lrelu(xl0 + xr0) + a1 * lrelu(xl1 + xr1);
        float wsl = expf(fminf(ee, 75.f));
        float s = g_sdec[w] + wsl;
        float A0 = g_accdec[2 * w] + wsl * xl0;
        float A1 = g_accdec[2 * w + 1] + wsl * xl1;
        float inv = 1.f / (s + 1e-16f);
        float l0 = A0 * inv + __ldg(&biasd[0]);
        float l1 = A1 * inv + __ldg(&biasd[1]);
        float z0 = (l0 + gum[2 * w]) * 2.0f;
        float z1 = (l1 + gum[2 * w + 1]) * 2.0f;
        k = (z0 >= z1) ? 0 : 1;
        float du = (k == 0) ? (z1 - z0) : (z0 - z1);
        float p = 1.f / (1.f + expf(du));
        volatile float t = 1.0f + p;
        g = t - p;
    }

    const int* csr = k ? g_csr1 : g_csr0;
    const int* off = k ? g_off1 : g_off0;
    int beg = off[w], end = off[w + 1];

    float4 a4 = *(const float4*)(att + lane * 4);
    const float4* xlp = (const float4*)g_xl;
    float4 r4 = *((const float4*)(g_xr) + (size_t)w * 32 + lane);

    // self loop
    float4 v = xlp[(size_t)w * 32 + lane];
    float p = a4.x * lrelu(v.x + r4.x) + a4.y * lrelu(v.y + r4.y) +
              a4.z * lrelu(v.z + r4.z) + a4.w * lrelu(v.w + r4.w);
    float e = warp_sum(p);
    float wt = __expf(fminf(e, 75.f));
    float s = wt;
    float4 acc = make_float4(wt * v.x, wt * v.y, wt * v.z, wt * v.w);

#pragma unroll 2
    for (int j = beg; j < end; j++) {
        int src = __ldg(&csr[j]);
        float4 u = xlp[(size_t)src * 32 + lane];
        float q = a4.x * lrelu(u.x + r4.x) + a4.y * lrelu(u.y + r4.y) +
                  a4.z * lrelu(u.z + r4.z) + a4.w * lrelu(u.w + r4.w);
        float e2 = warp_sum(q);
        float w2 = __expf(fminf(e2, 75.f));
        s += w2;
        acc.x += w2 * u.x; acc.y += w2 * u.y; acc.z += w2 * u.z; acc.w += w2 * u.w;
    }

    float inv = g / (s + 1e-16f);
    float4 b4 = *(const float4*)(bias + lane * 4);
    float4 o4 = make_float4(acc.x * inv + b4.x * g, acc.y * inv + b4.y * g,
                            acc.z * inv + b4.z * g, acc.w * inv + b4.w * g);
    *((float4*)out + (size_t)w * 32 + lane) = o4;
}

// ---------------- launcher ----------------
extern "C" void kernel_launch(void* const* d_in, const int* in_sizes, int n_in,
                              void* d_out, int out_size) {
    const float* x      = (const float*)d_in[0];
    const int*   e_dec  = (const int*)d_in[1];
    const int*   e0     = (const int*)d_in[2];
    const int*   e1     = (const int*)d_in[3];
    const float* gum    = (const float*)d_in[4];
    const float* Wl_g   = (const float*)d_in[5];
    const float* Wr_g   = (const float*)d_in[6];
    const float* bl_g   = (const float*)d_in[7];
    const float* br_g   = (const float*)d_in[8];
    const float* att_g  = (const float*)d_in[9];
    const float* bias_g = (const float*)d_in[10];
    const float* Wl_d   = (const float*)d_in[11];
    const float* Wr_d   = (const float*)d_in[12];
    const float* bl_d   = (const float*)d_in[13];
    const float* br_d   = (const float*)d_in[14];
    const float* att_d  = (const float*)d_in[15];
    const float* bias_d = (const float*)d_in[16];
    float* out = (float*)d_out;

    const int n = in_sizes[0] / 128;
    const int E = in_sizes[1] / 2;
    const int nb = (n + 511) / 512;
    const int eBlocks = (E + 255) / 256;

    cudaFuncSetAttribute(k_mma, cudaFuncAttributeMaxDynamicSharedMemorySize, SM_GEMM_TOTAL);

    k_detect<<<1, 32>>>(e_dec);
    k_zero<<<(2 * n + 255) / 256, 256>>>(n);
    k_prepW<<<128, 256>>>(Wl_g, Wr_g);

    const int gBlocks = (n + 127) / 128;
    k_mma<<<gBlocks, 256, SM_GEMM_TOTAL>>>(x, bl_g, 0, n);
    k_mma<<<gBlocks, 256, SM_GEMM_TOTAL>>>(x, br_g, 1, n);
    k_gemmd<<<(n + 7) / 8, 256>>>(x, Wl_d, Wr_d, bl_d, br_d, n);

    k_edges<<<3 * eBlocks, 256>>>(e0, e1, e_dec, att_d, E, eBlocks);

    k_scan1<<<2 * nb, 512>>>(n, nb);
    k_scan2<<<1, 256>>>(n, nb);
    k_scan3<<<2 * nb, 512>>>(n, nb);

    k_scatter2<<<2 * eBlocks, 256>>>(e0, e1, E, eBlocks);

    k_agg<<<(n + 7) / 8, 256>>>(att_g, bias_g, gum, att_d, bias_d, out, n);
}